// round 9
// baseline (speedup 1.0000x reference)
#include <cuda_runtime.h>
#include <cuda_bf16.h>

// preds:   (16, 19, 512, 512) float32 = 79,691,776 elems
// targets: (16, 1024, 1024) labels in [0,19) (delivered as int32)
// grid 16 -> 32x32 cells/batch, 16x16 px each.
//
// k_presence: one warp per 4 cells, 16 independent int4 loads (MLP=16),
//             uint4 mask store.
// k_loss: 38-iter grid-stride. Per elem: 1 MUFU (ex2) + deg-5 ln(1+t) poly
//         (constant term hoisted to N*B0, added once at the end);
//         relu(se ? -x : x) = 0.5*(|x| + s*x), s=+-1 per float4.
//         In-loop L1-hit mask read (overlaps with math). Final reduction
//         fused via last-block ticket.

#define N_ELEMS   79691776
#define N4        (N_ELEMS / 4)
#define NBLK      2048
#define NTHR      256
#define LOSS_STRIDE (NBLK * NTHR)       // 524288 float4s; N4/LOSS_STRIDE = 38
#define LOSS_ITERS  38

// deg-5 minimax (Chebyshev-derived) for ln(1+t), t in [0,1]:
// ln(1+t) ~= B0 + t*(B1 + t*(B2 + t*(B3 + t*(B4 + t*B5)))),  |err| <= ~1e-5
#define B0_D 9.8e-6
#define B1_F 0.9992366f
#define B2_F (-0.4902340f)
#define B3_F 0.2852784f
#define B4_F (-0.1315872f)
#define B5_F 0.0304512f

__device__ unsigned g_masks[16384];
__device__ double   g_partial[NBLK];
__device__ unsigned g_fin = 0;

__device__ __forceinline__ float ex2_(float x) { float r; asm("ex2.approx.f32 %0, %1;" : "=f"(r) : "f"(x)); return r; }

// ---------------------------------------------------------------------------
// Kernel 1: per-cell class-presence bitmask (stride-2 NN downsample).
// One warp per 4 consecutive cells; 16 independent int4 loads per thread.
// ---------------------------------------------------------------------------
__global__ void __launch_bounds__(256) k_presence(const int4* __restrict__ t4) {
    int gwarp = (blockIdx.x * blockDim.x + threadIdx.x) >> 5;  // 0..4095
    int lane  = threadIdx.x & 31;
    int c0    = gwarp << 2;            // 4 consecutive cells (same batch/row)
    int b     = c0 >> 10;
    int rest  = c0 & 1023;
    int ch    = rest >> 5;
    int cw    = rest & 31;             // multiple of 4

    int base = (b << 18) + (ch << 13) + (cw << 3);

    int4 q[4][4];
#pragma unroll
    for (int k = 0; k < 4; ++k) {
        int e = lane + (k << 5);       // 0..127: 16 rows x 8 int4/row
        int i = e >> 3, jj = e & 7;
        int roff = (i << 9) + jj;      // row stride 512 int4s (2 orig rows)
#pragma unroll
        for (int j = 0; j < 4; ++j)
            q[j][k] = __ldg(&t4[base + (j << 3) + roff]);
    }
    unsigned m[4];
#pragma unroll
    for (int j = 0; j < 4; ++j) {
        unsigned mm = 0;
#pragma unroll
        for (int k = 0; k < 4; ++k)
            mm |= (1u << (q[j][k].x & 31)) | (1u << (q[j][k].z & 31));
        m[j] = __reduce_or_sync(0xFFFFFFFFu, mm);
    }
    if (lane == 0)
        *reinterpret_cast<uint4*>(&g_masks[c0]) = make_uint4(m[0], m[1], m[2], m[3]);
}

// per-element math: al += t*q(t)  (= ln(1+e^{-|x|}) - B0),  A += |x|
__device__ __forceinline__ void term(float x, float& al, float& A) {
    float t = ex2_(fabsf(x) * -1.4426950408889634f);
    float q = fmaf(B5_F, t, B4_F);
    q = fmaf(q, t, B3_F);
    q = fmaf(q, t, B2_F);
    q = fmaf(q, t, B1_F);
    al = fmaf(q, t, al);
    A += fabsf(x);
}

// ---------------------------------------------------------------------------
// Kernel 2: streaming loss + fused final reduction.
// ---------------------------------------------------------------------------
__global__ void __launch_bounds__(NTHR) k_loss(const float4* __restrict__ p4,
                                               float* __restrict__ out) {
    const int tid  = threadIdx.x;
    const int gtid = blockIdx.x * NTHR + tid;

    // loop-invariant geometry (stride covers exactly 8 (b,c)-planes)
    int lin    = gtid << 2;
    int w      = lin & 511;
    int h      = (lin >> 9) & 511;
    int cellhw = ((h >> 4) << 5) + (w >> 4);
    int c      = gtid >> 16;               // class at iter 0 (b = 0)
    const unsigned* mp = g_masks + cellhw;

    float al0 = 0.f, al1 = 0.f, A0 = 0.f, A1 = 0.f, S = 0.f;
#pragma unroll 2
    for (int k = 0; k < LOSS_ITERS; ++k) {
        float4 v = __ldcs(p4 + gtid + k * LOSS_STRIDE);
        unsigned se = (mp[0] >> c) & 1u;
        float s = __int_as_float(0x3F800000u | (se << 31));   // +-1
        term(v.x, al0, A0); term(v.y, al1, A1);
        term(v.z, al0, A0); term(v.w, al1, A1);
        float dot = (v.x + v.y) + (v.z + v.w);
        S = fmaf(s, dot, S);
        c += 8; if (c >= 19) { c -= 19; mp += 1024; }
    }

    // thread total: ln-part + 0.5*(sum|x| + sum s*x)   (B0*N added at the end)
    double acc = (double)(al0 + al1) + 0.5 * ((double)(A0 + A1) + (double)S);

    // deterministic block reduction -> g_partial
    __shared__ double smem[NTHR / 32];
    __shared__ int s_last;
    for (int o = 16; o > 0; o >>= 1) acc += __shfl_down_sync(0xFFFFFFFFu, acc, o);
    if ((tid & 31) == 0) smem[tid >> 5] = acc;
    __syncthreads();
    if (tid < (NTHR / 32)) {
        double a = smem[tid];
        for (int o = (NTHR / 64); o > 0; o >>= 1) a += __shfl_down_sync(0xFFu, a, o);
        if (tid == 0) g_partial[blockIdx.x] = a;
    }

    // last block: final deterministic reduction + write + counter reset
    if (tid == 0) {
        __threadfence();
        unsigned old = atomicAdd(&g_fin, 1u);
        s_last = (old == NBLK - 1);
    }
    __syncthreads();
    if (s_last) {
        __threadfence();
        __shared__ double smem2[NTHR / 32];
        double a = 0.0;
        for (int i = tid; i < NBLK; i += NTHR) a += g_partial[i];
        for (int o = 16; o > 0; o >>= 1) a += __shfl_down_sync(0xFFFFFFFFu, a, o);
        if ((tid & 31) == 0) smem2[tid >> 5] = a;
        __syncthreads();
        if (tid < (NTHR / 32)) {
            double v = smem2[tid];
            for (int o = (NTHR / 64); o > 0; o >>= 1) v += __shfl_down_sync(0xFFu, v, o);
            if (tid == 0) {
                double total = v + (double)N_ELEMS * B0_D;
                out[0] = (float)(total * (1.0 / (double)N_ELEMS));
                g_fin = 0;   // reset for next run / graph replay
            }
        }
    }
}

extern "C" void kernel_launch(void* const* d_in, const int* in_sizes, int n_in,
                              void* d_out, int out_size) {
    const float4* preds   = (const float4*)d_in[0];
    const int4*   targets = (const int4*)d_in[1];
    float*        out     = (float*)d_out;
    k_presence<<<512, 256>>>(targets);
    k_loss<<<NBLK, NTHR>>>(preds, out);
}